// round 2
// baseline (speedup 1.0000x reference)
#include <cuda_runtime.h>
#include <cstdint>

// Problem constants (fixed-shape problem)
#define Bn 16
#define Nn 10000
#define Tn 24
#define Hn 32
#define On 16
#define Mn (Bn*Nn)          // 160000 rows
#define G3H 96              // 3*H

// ---------------- device scratch (no allocations allowed) ----------------
__device__ float g_h   [Mn*Hn];   // GRU output, layout [n][b][32]
__device__ float g_xw1 [Mn*Hn];   // conv1 x@W1,   [n][b][32]
__device__ float g_out1[Mn*Hn];   // conv1 result, [n][b][32]
__device__ float g_xw2 [Mn*On];   // conv2 x@W2,   [n][b][16]
__device__ float g_out2[Mn*On];   // conv2 result, [n][b][16]
__device__ float g_deg [Nn];
__device__ float g_dinv[Nn];

// ---------------- fast activations ----------------
__device__ __forceinline__ float fsig(float x){
    return __fdividef(1.f, 1.f + __expf(-x));
}
__device__ __forceinline__ float ftanh(float x){
    x = fminf(fmaxf(x, -15.f), 15.f);        // avoid inf*0 NaN
    float e = __expf(2.f*x);
    return (e - 1.f) * __fdividef(1.f, e + 1.f);
}

// ---------------- degree / norm ----------------
__global__ void deg_init_kernel(){
    int i = blockIdx.x*blockDim.x + threadIdx.x;
    if (i < Nn) g_deg[i] = 1.f;               // self-loop weight
}
__global__ void deg_acc_kernel(const int* __restrict__ ei,
                               const float* __restrict__ ew, int E){
    int e = blockIdx.x*blockDim.x + threadIdx.x;
    if (e < E) atomicAdd(&g_deg[ei[E + e]], ew[e]);
}
__global__ void dinv_kernel(){
    int i = blockIdx.x*blockDim.x + threadIdx.x;
    if (i < Nn){
        float d = g_deg[i];
        g_dinv[i] = d > 0.f ? rsqrtf(d) : 0.f;
    }
}

// ---------------- GRU: TWO sequences per thread (amortize weight LDS) ----------------
#define GRU_TPB 256
#define GRU_SEQS (Mn/2)      // 80000 threads

__global__ __launch_bounds__(GRU_TPB,1)
void gru_kernel(const float* __restrict__ x,
                const float* __restrict__ w_ih, const float* __restrict__ w_hh,
                const float* __restrict__ b_ih, const float* __restrict__ b_hh)
{
    __shared__ float s_whh[G3H*Hn];
    __shared__ float s_wih[G3H], s_bih[G3H], s_bhh[G3H];
    int tid = threadIdx.x;
    for (int i = tid; i < G3H*Hn; i += GRU_TPB) s_whh[i] = w_hh[i];
    if (tid < G3H){ s_wih[tid]=w_ih[tid]; s_bih[tid]=b_ih[tid]; s_bhh[tid]=b_hh[tid]; }
    __syncthreads();

    int g = blockIdx.x*GRU_TPB + tid;
    if (g >= GRU_SEQS) return;
    int mA = 2*g, mB = 2*g + 1;
    const float* xsA = x + (size_t)mA * Tn;
    const float* xsB = x + (size_t)mB * Tn;

    float hA[Hn], hB[Hn];
#pragma unroll
    for (int k = 0; k < Hn; k++){ hA[k] = 0.f; hB[k] = 0.f; }

#pragma unroll 1
    for (int t = 0; t < Tn; t++){
        float xa = __ldg(xsA + t);
        float xb = __ldg(xsB + t);
        float nA[Hn], nB[Hn];
#pragma unroll
        for (int j = 0; j < Hn; j++){
            float arA0 = s_bhh[j],    arA1 = 0.f, arB0 = s_bhh[j],    arB1 = 0.f;
            float azA0 = s_bhh[32+j], azA1 = 0.f, azB0 = s_bhh[32+j], azB1 = 0.f;
            float anA0 = s_bhh[64+j], anA1 = 0.f, anB0 = s_bhh[64+j], anB1 = 0.f;
            const float4* wr = (const float4*)(s_whh +  j      *Hn);
            const float4* wz = (const float4*)(s_whh + (32+j)  *Hn);
            const float4* wn = (const float4*)(s_whh + (64+j)  *Hn);
#pragma unroll
            for (int k4 = 0; k4 < 8; k4++){
                float4 w = wr[k4];
                arA0 += hA[4*k4+0]*w.x; arA1 += hA[4*k4+1]*w.y;
                arA0 += hA[4*k4+2]*w.z; arA1 += hA[4*k4+3]*w.w;
                arB0 += hB[4*k4+0]*w.x; arB1 += hB[4*k4+1]*w.y;
                arB0 += hB[4*k4+2]*w.z; arB1 += hB[4*k4+3]*w.w;
            }
#pragma unroll
            for (int k4 = 0; k4 < 8; k4++){
                float4 w = wz[k4];
                azA0 += hA[4*k4+0]*w.x; azA1 += hA[4*k4+1]*w.y;
                azA0 += hA[4*k4+2]*w.z; azA1 += hA[4*k4+3]*w.w;
                azB0 += hB[4*k4+0]*w.x; azB1 += hB[4*k4+1]*w.y;
                azB0 += hB[4*k4+2]*w.z; azB1 += hB[4*k4+3]*w.w;
            }
#pragma unroll
            for (int k4 = 0; k4 < 8; k4++){
                float4 w = wn[k4];
                anA0 += hA[4*k4+0]*w.x; anA1 += hA[4*k4+1]*w.y;
                anA0 += hA[4*k4+2]*w.z; anA1 += hA[4*k4+3]*w.w;
                anB0 += hB[4*k4+0]*w.x; anB1 += hB[4*k4+1]*w.y;
                anB0 += hB[4*k4+2]*w.z; anB1 += hB[4*k4+3]*w.w;
            }
            float wi_r = s_wih[j],    bi_r = s_bih[j];
            float wi_z = s_wih[32+j], bi_z = s_bih[32+j];
            float wi_n = s_wih[64+j], bi_n = s_bih[64+j];

            float rA = fsig (xa*wi_r + bi_r + (arA0+arA1));
            float zA = fsig (xa*wi_z + bi_z + (azA0+azA1));
            float vA = ftanh(xa*wi_n + bi_n + rA*(anA0+anA1));
            nA[j] = vA + zA*(hA[j] - vA);

            float rB = fsig (xb*wi_r + bi_r + (arB0+arB1));
            float zB = fsig (xb*wi_z + bi_z + (azB0+azB1));
            float vB = ftanh(xb*wi_n + bi_n + rB*(anB0+anB1));
            nB[j] = vB + zB*(hB[j] - vB);
        }
#pragma unroll
        for (int j = 0; j < Hn; j++){ hA[j] = nA[j]; hB[j] = nB[j]; }
    }

    // write h in [n][b][32] layout for edge-contiguous GCN rows
    {
        int b = mA / Nn, n = mA % Nn;
        float* dst = g_h + ((size_t)n*Bn + b)*Hn;
#pragma unroll
        for (int k = 0; k < Hn; k += 4)
            *(float4*)(dst + k) = make_float4(hA[k], hA[k+1], hA[k+2], hA[k+3]);
    }
    {
        int b = mB / Nn, n = mB % Nn;
        float* dst = g_h + ((size_t)n*Bn + b)*Hn;
#pragma unroll
        for (int k = 0; k < Hn; k += 4)
            *(float4*)(dst + k) = make_float4(hB[k], hB[k+1], hB[k+2], hB[k+3]);
    }
}

// ---------------- dense matmul + self-loop init (+ optional bias+relu on input) ----------------
template<int CIN, int COUT, bool RELU>
__global__ void mm_init_kernel(const float* __restrict__ in,
                               const float* __restrict__ W,
                               const float* __restrict__ bin,
                               float* __restrict__ xw,
                               float* __restrict__ outbuf)
{
    __shared__ float sW[CIN*COUT];
    __shared__ float sb[CIN];
    int tid = threadIdx.x;
    for (int i = tid; i < CIN*COUT; i += blockDim.x) sW[i] = W[i];
    if (RELU && tid < CIN) sb[tid] = bin[tid];
    __syncthreads();

    int r = blockIdx.x*blockDim.x + tid;
    if (r >= Mn) return;
    int n = r / Bn;
    float di = g_dinv[n];
    float dd = di*di;                         // self-loop norm

    float v[CIN];
#pragma unroll
    for (int i = 0; i < CIN; i += 4){
        float4 t4 = *(const float4*)(in + (size_t)r*CIN + i);
        v[i]=t4.x; v[i+1]=t4.y; v[i+2]=t4.z; v[i+3]=t4.w;
    }
    if (RELU){
#pragma unroll
        for (int i = 0; i < CIN; i++) v[i] = fmaxf(v[i] + sb[i], 0.f);
    }
    float acc[COUT];
#pragma unroll
    for (int o = 0; o < COUT; o++) acc[o] = 0.f;
#pragma unroll
    for (int i = 0; i < CIN; i++){
        float vi = v[i];
#pragma unroll
        for (int o = 0; o < COUT; o++) acc[o] += vi * sW[i*COUT + o];
    }
    float* px = xw     + (size_t)r*COUT;
    float* po = outbuf + (size_t)r*COUT;
#pragma unroll
    for (int o = 0; o < COUT; o += 4){
        *(float4*)(px+o) = make_float4(acc[o],    acc[o+1],    acc[o+2],    acc[o+3]);
        *(float4*)(po+o) = make_float4(dd*acc[o], dd*acc[o+1], dd*acc[o+2], dd*acc[o+3]);
    }
}

// ---------------- edge scatter: one warp per edge, vectorized fp32 RED ----------------
__device__ __forceinline__ void red4(float* p, float4 v){
    asm volatile("red.global.add.v4.f32 [%0], {%1, %2, %3, %4};"
                 :: "l"(p), "f"(v.x), "f"(v.y), "f"(v.z), "f"(v.w) : "memory");
}

template<int C>
__global__ void scatter_kernel(const int* __restrict__ ei,
                               const float* __restrict__ ew,
                               const float* __restrict__ xw,
                               float* __restrict__ out, int E)
{
    int g    = blockIdx.x*blockDim.x + threadIdx.x;
    int warp = g >> 5;
    int lane = g & 31;
    if (warp >= E) return;

    int src = 0, tgt = 0; float nrm = 0.f;
    if (lane == 0){
        src = ei[warp];
        tgt = ei[E + warp];
        nrm = g_dinv[src] * ew[warp] * g_dinv[tgt];
    }
    src = __shfl_sync(0xffffffffu, src, 0);
    tgt = __shfl_sync(0xffffffffu, tgt, 0);
    nrm = __shfl_sync(0xffffffffu, nrm, 0);

    const float4* s = (const float4*)(xw + (size_t)src*(Bn*C));
    float*        d = out + (size_t)tgt*(Bn*C);
#pragma unroll
    for (int i = 0; i < (Bn*C)/128; i++){
        float4 v = s[lane + 32*i];
        v.x *= nrm; v.y *= nrm; v.z *= nrm; v.w *= nrm;
        red4(d + 4*(lane + 32*i), v);
    }
}

// ---------------- final linear head + [b][n] transpose ----------------
__global__ void final_kernel(const float* __restrict__ b2,
                             const float* __restrict__ Wfc,
                             const float* __restrict__ bfc,
                             float* __restrict__ y)
{
    int r = blockIdx.x*blockDim.x + threadIdx.x;
    if (r >= Mn) return;
    int n = r / Bn, b = r % Bn;
    const float* row = g_out2 + (size_t)r*On;
    float acc = bfc[0];
#pragma unroll
    for (int o = 0; o < On; o++) acc += (row[o] + b2[o]) * Wfc[o];
    y[(size_t)b*Nn + n] = acc;
}

// ---------------- launch ----------------
extern "C" void kernel_launch(void* const* d_in, const int* in_sizes, int n_in,
                              void* d_out, int out_size)
{
    const float* x    = (const float*)d_in[0];
    const int*   ei   = (const int*)  d_in[1];
    const float* ew   = (const float*)d_in[2];
    const float* w_ih = (const float*)d_in[3];
    const float* w_hh = (const float*)d_in[4];
    const float* b_ih = (const float*)d_in[5];
    const float* b_hh = (const float*)d_in[6];
    const float* W1   = (const float*)d_in[7];
    const float* b1   = (const float*)d_in[8];
    const float* W2   = (const float*)d_in[9];
    const float* b2   = (const float*)d_in[10];
    const float* Wfc  = (const float*)d_in[11];
    const float* bfc  = (const float*)d_in[12];
    float* y = (float*)d_out;
    int E = in_sizes[2];

    // resolve __device__ scratch addresses (not an allocation)
    float *p_h, *p_xw1, *p_out1, *p_xw2, *p_out2;
    cudaGetSymbolAddress((void**)&p_h,    g_h);
    cudaGetSymbolAddress((void**)&p_xw1,  g_xw1);
    cudaGetSymbolAddress((void**)&p_out1, g_out1);
    cudaGetSymbolAddress((void**)&p_xw2,  g_xw2);
    cudaGetSymbolAddress((void**)&p_out2, g_out2);

    // 1) gcn_norm
    deg_init_kernel<<<(Nn+255)/256, 256>>>();
    deg_acc_kernel <<<(E +255)/256, 256>>>(ei, ew, E);
    dinv_kernel    <<<(Nn+255)/256, 256>>>();

    // 2) GRU temporal encoder (2 sequences per thread)
    gru_kernel<<<(GRU_SEQS + GRU_TPB - 1)/GRU_TPB, GRU_TPB>>>(x, w_ih, w_hh, b_ih, b_hh);

    // 3) conv1: xw1 = h@W1, out1 init = dinv^2*xw1 (self loop), then edge scatter
    mm_init_kernel<Hn, Hn, false><<<(Mn+127)/128, 128>>>(p_h, W1, nullptr, p_xw1, p_out1);
    scatter_kernel<Hn><<<((size_t)E*32 + 255)/256, 256>>>(ei, ew, p_xw1, p_out1, E);

    // 4) conv2: relu(out1+b1)@W2, self-loop init, edge scatter
    mm_init_kernel<Hn, On, true><<<(Mn+127)/128, 128>>>(p_out1, W2, b1, p_xw2, p_out2);
    scatter_kernel<On><<<((size_t)E*32 + 255)/256, 256>>>(ei, ew, p_xw2, p_out2, E);

    // 5) head: (out2+b2)@Wfc + bfc, transpose to [b][n]
    final_kernel<<<(Mn+255)/256, 256>>>(b2, Wfc, bfc, y);
}

// round 3
// speedup vs baseline: 1.7836x; 1.7836x over previous
#include <cuda_runtime.h>
#include <cstdint>

// Problem constants (fixed-shape problem)
#define Bn 16
#define Nn 10000
#define Tn 24
#define Hn 32
#define On 16
#define Mn (Bn*Nn)          // 160000 rows
#define G3H 96              // 3*H

// ---------------- device scratch (no allocations allowed) ----------------
__device__ float g_h   [Mn*Hn];   // GRU output, layout [n][b][32]
__device__ float g_xw1 [Mn*Hn];   // conv1 x@W1,   [n][b][32]
__device__ float g_out1[Mn*Hn];   // conv1 result, [n][b][32]
__device__ float g_xw2 [Mn*On];   // conv2 x@W2,   [n][b][16]
__device__ float g_out2[Mn*On];   // conv2 result, [n][b][16]
__device__ float g_deg [Nn];
__device__ float g_dinv[Nn];

// ---------------- GRU weights in constant memory (uniform LDCU path, off L1TEX) ----
__constant__ float4 c_whh4[G3H*Hn/4];   // w_hh rows, 8 float4 per row
__constant__ float  c_wih[G3H];
__constant__ float  c_bih[G3H];
__constant__ float  c_bhh[G3H];

// ---------------- fast activations ----------------
__device__ __forceinline__ float fsig(float x){
    return __fdividef(1.f, 1.f + __expf(-x));
}
__device__ __forceinline__ float ftanh(float x){
    x = fminf(fmaxf(x, -15.f), 15.f);        // avoid inf*0 NaN
    float e = __expf(2.f*x);
    return (e - 1.f) * __fdividef(1.f, e + 1.f);
}

// ---------------- degree / norm ----------------
__global__ void deg_init_kernel(){
    int i = blockIdx.x*blockDim.x + threadIdx.x;
    if (i < Nn) g_deg[i] = 1.f;               // self-loop weight
}
__global__ void deg_acc_kernel(const int* __restrict__ ei,
                               const float* __restrict__ ew, int E){
    int e = blockIdx.x*blockDim.x + threadIdx.x;
    if (e < E) atomicAdd(&g_deg[ei[E + e]], ew[e]);
}
__global__ void dinv_kernel(){
    int i = blockIdx.x*blockDim.x + threadIdx.x;
    if (i < Nn){
        float d = g_deg[i];
        g_dinv[i] = d > 0.f ? rsqrtf(d) : 0.f;
    }
}

// ---------------- GRU: one sequence per thread, weights via constant/uniform port ----
#define GRU_TPB 256

__global__ __launch_bounds__(GRU_TPB,1)
void gru_kernel(const float* __restrict__ x)
{
    int m = blockIdx.x*GRU_TPB + threadIdx.x;   // Mn = 625*256 exactly
    const float* xs = x + (size_t)m * Tn;

    float h[Hn];
#pragma unroll
    for (int k = 0; k < Hn; k++) h[k] = 0.f;

    float xt = __ldg(xs);                        // prefetch t=0

#pragma unroll 1
    for (int t = 0; t < Tn; t++){
        float xt_next = (t+1 < Tn) ? __ldg(xs + t + 1) : 0.f;
        float hn[Hn];
#pragma unroll
        for (int j = 0; j < Hn; j++){
            float ar0 = c_bhh[j],      ar1 = 0.f;
            float az0 = c_bhh[32+j],   az1 = 0.f;
            float an0 = c_bhh[64+j],   an1 = 0.f;
#pragma unroll
            for (int k4 = 0; k4 < 8; k4++){
                float4 w = c_whh4[j*8 + k4];
                ar0 += h[4*k4+0]*w.x; ar1 += h[4*k4+1]*w.y;
                ar0 += h[4*k4+2]*w.z; ar1 += h[4*k4+3]*w.w;
            }
#pragma unroll
            for (int k4 = 0; k4 < 8; k4++){
                float4 w = c_whh4[(32+j)*8 + k4];
                az0 += h[4*k4+0]*w.x; az1 += h[4*k4+1]*w.y;
                az0 += h[4*k4+2]*w.z; az1 += h[4*k4+3]*w.w;
            }
#pragma unroll
            for (int k4 = 0; k4 < 8; k4++){
                float4 w = c_whh4[(64+j)*8 + k4];
                an0 += h[4*k4+0]*w.x; an1 += h[4*k4+1]*w.y;
                an0 += h[4*k4+2]*w.z; an1 += h[4*k4+3]*w.w;
            }
            float r  = fsig (xt*c_wih[j]    + c_bih[j]    + (ar0+ar1));
            float z  = fsig (xt*c_wih[32+j] + c_bih[32+j] + (az0+az1));
            float nv = ftanh(xt*c_wih[64+j] + c_bih[64+j] + r*(an0+an1));
            hn[j] = nv + z*(h[j] - nv);
        }
#pragma unroll
        for (int j = 0; j < Hn; j++) h[j] = hn[j];
        xt = xt_next;
    }

    // write h in [n][b][32] layout for edge-contiguous GCN rows
    int b = m / Nn, n = m % Nn;
    float* dst = g_h + ((size_t)n*Bn + b)*Hn;
#pragma unroll
    for (int k = 0; k < Hn; k += 4)
        *(float4*)(dst + k) = make_float4(h[k], h[k+1], h[k+2], h[k+3]);
}

// ---------------- dense matmul + self-loop init (+ optional bias+relu on input) ----------------
template<int CIN, int COUT, bool RELU>
__global__ void mm_init_kernel(const float* __restrict__ in,
                               const float* __restrict__ W,
                               const float* __restrict__ bin,
                               float* __restrict__ xw,
                               float* __restrict__ outbuf)
{
    __shared__ float sW[CIN*COUT];
    __shared__ float sb[CIN];
    int tid = threadIdx.x;
    for (int i = tid; i < CIN*COUT; i += blockDim.x) sW[i] = W[i];
    if (RELU && tid < CIN) sb[tid] = bin[tid];
    __syncthreads();

    int r = blockIdx.x*blockDim.x + tid;
    if (r >= Mn) return;
    int n = r / Bn;
    float di = g_dinv[n];
    float dd = di*di;                         // self-loop norm

    float v[CIN];
#pragma unroll
    for (int i = 0; i < CIN; i += 4){
        float4 t4 = *(const float4*)(in + (size_t)r*CIN + i);
        v[i]=t4.x; v[i+1]=t4.y; v[i+2]=t4.z; v[i+3]=t4.w;
    }
    if (RELU){
#pragma unroll
        for (int i = 0; i < CIN; i++) v[i] = fmaxf(v[i] + sb[i], 0.f);
    }
    float acc[COUT];
#pragma unroll
    for (int o = 0; o < COUT; o++) acc[o] = 0.f;
#pragma unroll
    for (int i = 0; i < CIN; i++){
        float vi = v[i];
#pragma unroll
        for (int o = 0; o < COUT; o++) acc[o] += vi * sW[i*COUT + o];
    }
    float* px = xw     + (size_t)r*COUT;
    float* po = outbuf + (size_t)r*COUT;
#pragma unroll
    for (int o = 0; o < COUT; o += 4){
        *(float4*)(px+o) = make_float4(acc[o],    acc[o+1],    acc[o+2],    acc[o+3]);
        *(float4*)(po+o) = make_float4(dd*acc[o], dd*acc[o+1], dd*acc[o+2], dd*acc[o+3]);
    }
}

// ---------------- edge scatter: one warp per edge, vectorized fp32 RED ----------------
__device__ __forceinline__ void red4(float* p, float4 v){
    asm volatile("red.global.add.v4.f32 [%0], {%1, %2, %3, %4};"
                 :: "l"(p), "f"(v.x), "f"(v.y), "f"(v.z), "f"(v.w) : "memory");
}

template<int C>
__global__ void scatter_kernel(const int* __restrict__ ei,
                               const float* __restrict__ ew,
                               const float* __restrict__ xw,
                               float* __restrict__ out, int E)
{
    int g    = blockIdx.x*blockDim.x + threadIdx.x;
    int warp = g >> 5;
    int lane = g & 31;
    if (warp >= E) return;

    int src = 0, tgt = 0; float nrm = 0.f;
    if (lane == 0){
        src = ei[warp];
        tgt = ei[E + warp];
        nrm = g_dinv[src] * ew[warp] * g_dinv[tgt];
    }
    src = __shfl_sync(0xffffffffu, src, 0);
    tgt = __shfl_sync(0xffffffffu, tgt, 0);
    nrm = __shfl_sync(0xffffffffu, nrm, 0);

    const float4* s = (const float4*)(xw + (size_t)src*(Bn*C));
    float*        d = out + (size_t)tgt*(Bn*C);
#pragma unroll
    for (int i = 0; i < (Bn*C)/128; i++){
        float4 v = s[lane + 32*i];
        v.x *= nrm; v.y *= nrm; v.z *= nrm; v.w *= nrm;
        red4(d + 4*(lane + 32*i), v);
    }
}

// ---------------- final linear head + [b][n] transpose ----------------
__global__ void final_kernel(const float* __restrict__ b2,
                             const float* __restrict__ Wfc,
                             const float* __restrict__ bfc,
                             float* __restrict__ y)
{
    int r = blockIdx.x*blockDim.x + threadIdx.x;
    if (r >= Mn) return;
    int n = r / Bn, b = r % Bn;
    const float* row = g_out2 + (size_t)r*On;
    float acc = bfc[0];
#pragma unroll
    for (int o = 0; o < On; o++) acc += (row[o] + b2[o]) * Wfc[o];
    y[(size_t)b*Nn + n] = acc;
}

// ---------------- launch ----------------
extern "C" void kernel_launch(void* const* d_in, const int* in_sizes, int n_in,
                              void* d_out, int out_size)
{
    const float* x    = (const float*)d_in[0];
    const int*   ei   = (const int*)  d_in[1];
    const float* ew   = (const float*)d_in[2];
    const float* w_ih = (const float*)d_in[3];
    const float* w_hh = (const float*)d_in[4];
    const float* b_ih = (const float*)d_in[5];
    const float* b_hh = (const float*)d_in[6];
    const float* W1   = (const float*)d_in[7];
    const float* b1   = (const float*)d_in[8];
    const float* W2   = (const float*)d_in[9];
    const float* b2   = (const float*)d_in[10];
    const float* Wfc  = (const float*)d_in[11];
    const float* bfc  = (const float*)d_in[12];
    float* y = (float*)d_out;
    int E = in_sizes[2];

    // resolve __device__ scratch addresses (not an allocation)
    float *p_h, *p_xw1, *p_out1, *p_xw2, *p_out2;
    cudaGetSymbolAddress((void**)&p_h,    g_h);
    cudaGetSymbolAddress((void**)&p_xw1,  g_xw1);
    cudaGetSymbolAddress((void**)&p_out1, g_out1);
    cudaGetSymbolAddress((void**)&p_xw2,  g_xw2);
    cudaGetSymbolAddress((void**)&p_out2, g_out2);

    // 0) stage GRU weights into constant memory (D2D memcpy nodes, graph-capturable)
    cudaMemcpyToSymbolAsync(c_whh4, w_hh, G3H*Hn*sizeof(float), 0, cudaMemcpyDeviceToDevice);
    cudaMemcpyToSymbolAsync(c_wih,  w_ih, G3H*sizeof(float),    0, cudaMemcpyDeviceToDevice);
    cudaMemcpyToSymbolAsync(c_bih,  b_ih, G3H*sizeof(float),    0, cudaMemcpyDeviceToDevice);
    cudaMemcpyToSymbolAsync(c_bhh,  b_hh, G3H*sizeof(float),    0, cudaMemcpyDeviceToDevice);

    // 1) gcn_norm
    deg_init_kernel<<<(Nn+255)/256, 256>>>();
    deg_acc_kernel <<<(E +255)/256, 256>>>(ei, ew, E);
    dinv_kernel    <<<(Nn+255)/256, 256>>>();

    // 2) GRU temporal encoder
    gru_kernel<<<Mn/GRU_TPB, GRU_TPB>>>(x);

    // 3) conv1: xw1 = h@W1, out1 init = dinv^2*xw1 (self loop), then edge scatter
    mm_init_kernel<Hn, Hn, false><<<(Mn+127)/128, 128>>>(p_h, W1, nullptr, p_xw1, p_out1);
    scatter_kernel<Hn><<<((size_t)E*32 + 255)/256, 256>>>(ei, ew, p_xw1, p_out1, E);

    // 4) conv2: relu(out1+b1)@W2, self-loop init, edge scatter
    mm_init_kernel<Hn, On, true><<<(Mn+127)/128, 128>>>(p_out1, W2, b1, p_xw2, p_out2);
    scatter_kernel<On><<<((size_t)E*32 + 255)/256, 256>>>(ei, ew, p_xw2, p_out2, E);

    // 5) head: (out2+b2)@Wfc + bfc, transpose to [b][n]
    final_kernel<<<(Mn+255)/256, 256>>>(b2, Wfc, bfc, y);
}

// round 5
// speedup vs baseline: 2.1980x; 1.2324x over previous
#include <cuda_runtime.h>
#include <cstdint>

// Problem constants (fixed-shape problem)
#define Bn 16
#define Nn 10000
#define Tn 24
#define Hn 32
#define On 16
#define Mn (Bn*Nn)          // 160000 rows
#define G3H 96              // 3*H

// ---------------- device scratch (no allocations allowed) ----------------
__device__ float g_h   [Mn*Hn];   // GRU output, layout [n][b][32]
__device__ float g_xw1 [Mn*Hn];   // conv1 x@W1,   [n][b][32]
__device__ float g_out1[Mn*Hn];   // conv1 result, [n][b][32]
__device__ float g_xw2 [Mn*On];   // conv2 x@W2,   [n][b][16]
__device__ float g_out2[Mn*On];   // conv2 result, [n][b][16]
__device__ float g_deg [Nn];
__device__ float g_dinv[Nn];

// ---------------- packed f32x2 + misc asm helpers ----------------
typedef unsigned long long ull;

__device__ __forceinline__ ull ffma2(ull a, ull b, ull c){
    ull d;
    asm("fma.rn.f32x2 %0, %1, %2, %3;" : "=l"(d) : "l"(a), "l"(b), "l"(c));
    return d;
}
__device__ __forceinline__ ull packff(float lo, float hi){
    ull r;
    asm("mov.b64 %0, {%1, %2};" : "=l"(r) : "f"(lo), "f"(hi));
    return r;
}
__device__ __forceinline__ float hsum2(ull a, ull b){
    ull s; float lo, hi;
    asm("add.rn.f32x2 %0, %1, %2;" : "=l"(s) : "l"(a), "l"(b));
    asm("mov.b64 {%0, %1}, %2;" : "=f"(lo), "=f"(hi) : "l"(s));
    return lo + hi;
}
__device__ __forceinline__ float tanhap(float x){
    float y;
    asm("tanh.approx.f32 %0, %1;" : "=f"(y) : "f"(x));
    return y;
}
__device__ __forceinline__ void lds_v2b64(ull& a, ull& b, unsigned addr){
    asm volatile("ld.shared.v2.b64 {%0, %1}, [%2];" : "=l"(a), "=l"(b) : "r"(addr));
}

// ---------------- degree / norm ----------------
__global__ void deg_init_kernel(){
    int i = blockIdx.x*blockDim.x + threadIdx.x;
    if (i < Nn) g_deg[i] = 1.f;               // self-loop weight
}
__global__ void deg_acc_kernel(const int* __restrict__ ei,
                               const float* __restrict__ ew, int E){
    int e = blockIdx.x*blockDim.x + threadIdx.x;
    if (e < E) atomicAdd(&g_deg[ei[E + e]], ew[e]);
}
__global__ void dinv_kernel(){
    int i = blockIdx.x*blockDim.x + threadIdx.x;
    if (i < Nn){
        float d = g_deg[i];
        g_dinv[i] = d > 0.f ? rsqrtf(d) : 0.f;
    }
}

// ---------------- GRU: lane = hidden unit, register-resident weights ----------------
// Warp handles 32 sequences. Lane j keeps w_hh rows (r,z,n) for unit j in registers
// as f32x2 pairs. h state lives in per-warp SMEM ping-pong [s][k], read via
// broadcast LDS.128, written via conflict-free STS.32.
#define GRU_TPB   256
#define WPB       8                 // warps per block
#define WSM       2816              // floats per warp: 2*32*32 (h ping-pong) + 32*24 (x)
#define XOFF      2048
#define GRU_GRID  (Mn/(WPB*32))     // 625 blocks, exact

__global__ __launch_bounds__(GRU_TPB,1)
void gru_kernel(const float* __restrict__ x,
                const float* __restrict__ w_ih, const float* __restrict__ w_hh,
                const float* __restrict__ b_ih, const float* __restrict__ b_hh)
{
    extern __shared__ float sm[];
    const int lane = threadIdx.x & 31;
    const int wid  = threadIdx.x >> 5;
    float* hb = sm + wid*WSM;           // h ping-pong: [p][s][k] = p*1024 + s*32 + k
    float* xb = hb + XOFF;              // x: [s][t] = s*24 + t

    const int gw = blockIdx.x*WPB + wid;     // 625*8 = 5000 warps exactly
    const int m0 = gw*32;
    const int j  = lane;

    // ---- register-resident weights (one-time, tiny) ----
    ull wr[16], wz[16], wn[16];
    {
        const float2* w2 = (const float2*)w_hh;   // rows of 16 float2
#pragma unroll
        for (int k2 = 0; k2 < 16; k2++){
            float2 a = w2[( j      )*16 + k2];
            float2 b = w2[( 32 + j )*16 + k2];
            float2 c = w2[( 64 + j )*16 + k2];
            wr[k2] = packff(a.x, a.y);
            wz[k2] = packff(b.x, b.y);
            wn[k2] = packff(c.x, c.y);
        }
    }
    const float wir = w_ih[j], wiz = w_ih[32+j], win = w_ih[64+j];
    const float bR  = b_ih[j]    + b_hh[j];      // r-gate bias (x + h parts)
    const float bZ  = b_ih[32+j] + b_hh[32+j];
    const float bxn = b_ih[64+j];
    const float bhn = b_hh[64+j];

    // ---- stage x: lane loads its own sequence row (m0+lane) ----
    {
        const float4* xr4 = (const float4*)(x + (size_t)(m0 + lane)*Tn);
#pragma unroll
        for (int q = 0; q < 6; q++){
            float4 v = xr4[q];
            xb[lane*Tn + 4*q+0] = v.x; xb[lane*Tn + 4*q+1] = v.y;
            xb[lane*Tn + 4*q+2] = v.z; xb[lane*Tn + 4*q+3] = v.w;
        }
    }
    // ---- init h buffer 0 to zeros ----
#pragma unroll
    for (int i = lane; i < 1024; i += 32) hb[i] = 0.f;
    __syncwarp();

    int p = 0;
#pragma unroll 1
    for (int t = 0; t < Tn; t++){
        const float* hsrc = hb + p*1024;
        float*       hdst = hb + (p^1)*1024;
        const bool   last = (t == Tn-1);

#pragma unroll 2
        for (int s = 0; s < 32; s++){
            // broadcast-read h[s][0..31] as 16 f32x2
            ull hh[16];
            unsigned base = (unsigned)__cvta_generic_to_shared(hsrc + s*32);
            lds_v2b64(hh[0],  hh[1],  base +   0);
            lds_v2b64(hh[2],  hh[3],  base +  16);
            lds_v2b64(hh[4],  hh[5],  base +  32);
            lds_v2b64(hh[6],  hh[7],  base +  48);
            lds_v2b64(hh[8],  hh[9],  base +  64);
            lds_v2b64(hh[10], hh[11], base +  80);
            lds_v2b64(hh[12], hh[13], base +  96);
            lds_v2b64(hh[14], hh[15], base + 112);

            ull ar0 = packff(bR, 0.f),  ar1 = 0ull;
            ull az0 = packff(bZ, 0.f),  az1 = 0ull;
            ull an0 = packff(bhn, 0.f), an1 = 0ull;
#pragma unroll
            for (int k2 = 0; k2 < 16; k2 += 2){
                ar0 = ffma2(wr[k2],   hh[k2],   ar0);
                az0 = ffma2(wz[k2],   hh[k2],   az0);
                an0 = ffma2(wn[k2],   hh[k2],   an0);
                ar1 = ffma2(wr[k2+1], hh[k2+1], ar1);
                az1 = ffma2(wz[k2+1], hh[k2+1], az1);
                an1 = ffma2(wn[k2+1], hh[k2+1], an1);
            }
            float ar = hsum2(ar0, ar1);
            float az = hsum2(az0, az1);
            float an = hsum2(an0, an1);

            float xt   = xb[s*Tn + t];
            float hold = hsrc[s*32 + j];

            float r = fmaf(0.5f, tanhap(0.5f*fmaf(xt, wir, ar)), 0.5f);
            float z = fmaf(0.5f, tanhap(0.5f*fmaf(xt, wiz, az)), 0.5f);
            float xn = fmaf(xt, win, bxn);
            float nv = tanhap(fmaf(r, an, xn));
            float hnew = fmaf(z, hold - nv, nv);

            if (!last){
                hdst[s*32 + j] = hnew;
            } else {
                int m = m0 + s;
                int b = m / Nn, nn = m % Nn;
                g_h[((size_t)nn*Bn + b)*Hn + j] = hnew;   // coalesced across lanes
            }
        }
        __syncwarp();
        p ^= 1;
    }
}

// ---------------- dense matmul + self-loop init (+ optional bias+relu on input) ----------------
template<int CIN, int COUT, bool RELU>
__global__ void mm_init_kernel(const float* __restrict__ in,
                               const float* __restrict__ W,
                               const float* __restrict__ bin,
                               float* __restrict__ xw,
                               float* __restrict__ outbuf)
{
    __shared__ float sW[CIN*COUT];
    __shared__ float sb[CIN];
    int tid = threadIdx.x;
    for (int i = tid; i < CIN*COUT; i += blockDim.x) sW[i] = W[i];
    if (RELU && tid < CIN) sb[tid] = bin[tid];
    __syncthreads();

    int r = blockIdx.x*blockDim.x + tid;
    if (r >= Mn) return;
    int n = r / Bn;
    float di = g_dinv[n];
    float dd = di*di;                         // self-loop norm

    float v[CIN];
#pragma unroll
    for (int i = 0; i < CIN; i += 4){
        float4 t4 = *(const float4*)(in + (size_t)r*CIN + i);
        v[i]=t4.x; v[i+1]=t4.y; v[i+2]=t4.z; v[i+3]=t4.w;
    }
    if (RELU){
#pragma unroll
        for (int i = 0; i < CIN; i++) v[i] = fmaxf(v[i] + sb[i], 0.f);
    }
    float acc[COUT];
#pragma unroll
    for (int o = 0; o < COUT; o++) acc[o] = 0.f;
#pragma unroll
    for (int i = 0; i < CIN; i++){
        float vi = v[i];
#pragma unroll
        for (int o = 0; o < COUT; o++) acc[o] += vi * sW[i*COUT + o];
    }
    float* px = xw     + (size_t)r*COUT;
    float* po = outbuf + (size_t)r*COUT;
#pragma unroll
    for (int o = 0; o < COUT; o += 4){
        *(float4*)(px+o) = make_float4(acc[o],    acc[o+1],    acc[o+2],    acc[o+3]);
        *(float4*)(po+o) = make_float4(dd*acc[o], dd*acc[o+1], dd*acc[o+2], dd*acc[o+3]);
    }
}

// ---------------- edge scatter: one warp per edge, vectorized fp32 RED ----------------
__device__ __forceinline__ void red4(float* p, float4 v){
    asm volatile("red.global.add.v4.f32 [%0], {%1, %2, %3, %4};"
                 :: "l"(p), "f"(v.x), "f"(v.y), "f"(v.z), "f"(v.w) : "memory");
}

template<int C>
__global__ void scatter_kernel(const int* __restrict__ ei,
                               const float* __restrict__ ew,
                               const float* __restrict__ xw,
                               float* __restrict__ out, int E)
{
    int g    = blockIdx.x*blockDim.x + threadIdx.x;
    int warp = g >> 5;
    int lane = g & 31;
    if (warp >= E) return;

    int src = 0, tgt = 0; float nrm = 0.f;
    if (lane == 0){
        src = ei[warp];
        tgt = ei[E + warp];
        nrm = g_dinv[src] * ew[warp] * g_dinv[tgt];
    }
    src = __shfl_sync(0xffffffffu, src, 0);
    tgt = __shfl_sync(0xffffffffu, tgt, 0);
    nrm = __shfl_sync(0xffffffffu, nrm, 0);

    const float4* s = (const float4*)(xw + (size_t)src*(Bn*C));
    float*        d = out + (size_t)tgt*(Bn*C);
#pragma unroll
    for (int i = 0; i < (Bn*C)/128; i++){
        float4 v = s[lane + 32*i];
        v.x *= nrm; v.y *= nrm; v.z *= nrm; v.w *= nrm;
        red4(d + 4*(lane + 32*i), v);
    }
}

// ---------------- final linear head + [b][n] transpose ----------------
__global__ void final_kernel(const float* __restrict__ b2,
                             const float* __restrict__ Wfc,
                             const float* __restrict__ bfc,
                             float* __restrict__ y)
{
    int r = blockIdx.x*blockDim.x + threadIdx.x;
    if (r >= Mn) return;
    int n = r / Bn, b = r % Bn;
    const float* row = g_out2 + (size_t)r*On;
    float acc = bfc[0];
#pragma unroll
    for (int o = 0; o < On; o++) acc += (row[o] + b2[o]) * Wfc[o];
    y[(size_t)b*Nn + n] = acc;
}

// ---------------- launch ----------------
extern "C" void kernel_launch(void* const* d_in, const int* in_sizes, int n_in,
                              void* d_out, int out_size)
{
    const float* x    = (const float*)d_in[0];
    const int*   ei   = (const int*)  d_in[1];
    const float* ew   = (const float*)d_in[2];
    const float* w_ih = (const float*)d_in[3];
    const float* w_hh = (const float*)d_in[4];
    const float* b_ih = (const float*)d_in[5];
    const float* b_hh = (const float*)d_in[6];
    const float* W1   = (const float*)d_in[7];
    const float* b1   = (const float*)d_in[8];
    const float* W2   = (const float*)d_in[9];
    const float* b2   = (const float*)d_in[10];
    const float* Wfc  = (const float*)d_in[11];
    const float* bfc  = (const float*)d_in[12];
    float* y = (float*)d_out;
    int E = in_sizes[2];

    // resolve __device__ scratch addresses (not an allocation)
    float *p_h, *p_xw1, *p_out1, *p_xw2, *p_out2;
    cudaGetSymbolAddress((void**)&p_h,    g_h);
    cudaGetSymbolAddress((void**)&p_xw1,  g_xw1);
    cudaGetSymbolAddress((void**)&p_out1, g_out1);
    cudaGetSymbolAddress((void**)&p_xw2,  g_xw2);
    cudaGetSymbolAddress((void**)&p_out2, g_out2);

    // 1) gcn_norm
    deg_init_kernel<<<(Nn+255)/256, 256>>>();
    deg_acc_kernel <<<(E +255)/256, 256>>>(ei, ew, E);
    dinv_kernel    <<<(Nn+255)/256, 256>>>();

    // 2) GRU temporal encoder (warp-cooperative, register-resident weights)
    {
        const int smem = WPB * WSM * (int)sizeof(float);   // 90112 B
        cudaFuncSetAttribute(gru_kernel, cudaFuncAttributeMaxDynamicSharedMemorySize, smem);
        gru_kernel<<<GRU_GRID, GRU_TPB, smem>>>(x, w_ih, w_hh, b_ih, b_hh);  // 625 blocks
    }

    // 3) conv1: xw1 = h@W1, out1 init = dinv^2*xw1 (self loop), then edge scatter
    mm_init_kernel<Hn, Hn, false><<<(Mn+127)/128, 128>>>(p_h, W1, nullptr, p_xw1, p_out1);
    scatter_kernel<Hn><<<((size_t)E*32 + 255)/256, 256>>>(ei, ew, p_xw1, p_out1, E);

    // 4) conv2: relu(out1+b1)@W2, self-loop init, edge scatter
    mm_init_kernel<Hn, On, true><<<(Mn+127)/128, 128>>>(p_out1, W2, b1, p_xw2, p_out2);
    scatter_kernel<On><<<((size_t)E*32 + 255)/256, 256>>>(ei, ew, p_xw2, p_out2, E);

    // 5) head: (out2+b2)@Wfc + bfc, transpose to [b][n]
    final_kernel<<<(Mn+255)/256, 256>>>(b2, Wfc, bfc, y);
}

// round 6
// speedup vs baseline: 2.5292x; 1.1507x over previous
#include <cuda_runtime.h>
#include <cstdint>

// Problem constants (fixed-shape problem)
#define Bn 16
#define Nn 10000
#define Tn 24
#define Hn 32
#define On 16
#define Mn (Bn*Nn)          // 160000 rows
#define G3H 96              // 3*H

// ---------------- device scratch (no allocations allowed) ----------------
__device__ float g_h   [Mn*Hn];   // GRU output, layout [n][b][32]
__device__ float g_xw1 [Mn*Hn];   // conv1 x@W1,   [n][b][32]
__device__ float g_out1[Mn*Hn];   // conv1 result, [n][b][32]
__device__ float g_xw2 [Mn*On];   // conv2 x@W2,   [n][b][16]
__device__ float g_out2[Mn*On];   // conv2 result, [n][b][16]
__device__ float g_deg [Nn];
__device__ float g_dinv[Nn];

// ---------------- packed f32x2 + misc asm helpers ----------------
typedef unsigned long long ull;

__device__ __forceinline__ ull ffma2(ull a, ull b, ull c){
    ull d;
    asm("fma.rn.f32x2 %0, %1, %2, %3;" : "=l"(d) : "l"(a), "l"(b), "l"(c));
    return d;
}
__device__ __forceinline__ ull packff(float lo, float hi){
    ull r;
    asm("mov.b64 %0, {%1, %2};" : "=l"(r) : "f"(lo), "f"(hi));
    return r;
}
__device__ __forceinline__ float hsum2(ull a, ull b){
    ull s; float lo, hi;
    asm("add.rn.f32x2 %0, %1, %2;" : "=l"(s) : "l"(a), "l"(b));
    asm("mov.b64 {%0, %1}, %2;" : "=f"(lo), "=f"(hi) : "l"(s));
    return lo + hi;
}
__device__ __forceinline__ float tanhap(float x){
    float y;
    asm("tanh.approx.f32 %0, %1;" : "=f"(y) : "f"(x));
    return y;
}
__device__ __forceinline__ void lds_v2b64(ull& a, ull& b, unsigned addr){
    asm volatile("ld.shared.v2.b64 {%0, %1}, [%2];" : "=l"(a), "=l"(b) : "r"(addr));
}

// ---------------- degree / norm ----------------
__global__ void deg_init_kernel(){
    int i = blockIdx.x*blockDim.x + threadIdx.x;
    if (i < Nn) g_deg[i] = 1.f;               // self-loop weight
}
__global__ void deg_acc_kernel(const int* __restrict__ ei,
                               const float* __restrict__ ew, int E){
    int e = blockIdx.x*blockDim.x + threadIdx.x;
    if (e < E) atomicAdd(&g_deg[ei[E + e]], ew[e]);
}
__global__ void dinv_kernel(){
    int i = blockIdx.x*blockDim.x + threadIdx.x;
    if (i < Nn){
        float d = g_deg[i];
        g_dinv[i] = d > 0.f ? rsqrtf(d) : 0.f;
    }
}

// ---------------- GRU: lane = hidden unit, register-resident weights ----------------
// Warp handles 32 sequences. Lane j keeps w_hh rows (r,z,n) for unit j in registers
// as f32x2 pairs. h state lives in per-warp SMEM ping-pong [s][k].
// Block shape tuned for occupancy: 128 thr, 3 blocks/SM -> 12 warps/SM.
#define GRU_TPB   128
#define WPB       4                 // warps per block
#define WSM       2816              // floats per warp: 2*32*32 (h ping-pong) + 32*24 (x)
#define XOFF      2048
#define GRU_GRID  (Mn/(WPB*32))     // 1250 blocks, exact

__global__ __launch_bounds__(GRU_TPB,3)
void gru_kernel(const float* __restrict__ x,
                const float* __restrict__ w_ih, const float* __restrict__ w_hh,
                const float* __restrict__ b_ih, const float* __restrict__ b_hh)
{
    extern __shared__ float sm[];
    const int lane = threadIdx.x & 31;
    const int wid  = threadIdx.x >> 5;
    float* hb = sm + wid*WSM;           // h ping-pong: [p][s][k] = p*1024 + s*32 + k
    float* xb = hb + XOFF;              // x: [s][t] = s*24 + t

    const int gw = blockIdx.x*WPB + wid;     // 1250*4 = 5000 warps exactly
    const int m0 = gw*32;
    const int j  = lane;

    // ---- register-resident weights (one-time, tiny) ----
    ull wr[16], wz[16], wn[16];
    {
        const float2* w2 = (const float2*)w_hh;   // rows of 16 float2
#pragma unroll
        for (int k2 = 0; k2 < 16; k2++){
            float2 a = w2[( j      )*16 + k2];
            float2 b = w2[( 32 + j )*16 + k2];
            float2 c = w2[( 64 + j )*16 + k2];
            wr[k2] = packff(a.x, a.y);
            wz[k2] = packff(b.x, b.y);
            wn[k2] = packff(c.x, c.y);
        }
    }
    const float wir = w_ih[j], wiz = w_ih[32+j], win = w_ih[64+j];
    const float bR  = b_ih[j]    + b_hh[j];      // r-gate bias (x + h parts)
    const float bZ  = b_ih[32+j] + b_hh[32+j];
    const float bxn = b_ih[64+j];
    const float bhn = b_hh[64+j];

    // ---- stage x: lane loads its own sequence row (m0+lane) ----
    {
        const float4* xr4 = (const float4*)(x + (size_t)(m0 + lane)*Tn);
#pragma unroll
        for (int q = 0; q < 6; q++){
            float4 v = xr4[q];
            xb[lane*Tn + 4*q+0] = v.x; xb[lane*Tn + 4*q+1] = v.y;
            xb[lane*Tn + 4*q+2] = v.z; xb[lane*Tn + 4*q+3] = v.w;
        }
    }
    // ---- init h buffer 0 to zeros ----
#pragma unroll
    for (int i = lane; i < 1024; i += 32) hb[i] = 0.f;
    __syncwarp();

    int p = 0;
#pragma unroll 1
    for (int t = 0; t < Tn; t++){
        const float* hsrc = hb + p*1024;
        float*       hdst = hb + (p^1)*1024;
        const bool   last = (t == Tn-1);

#pragma unroll 2
        for (int s = 0; s < 32; s++){
            // broadcast-read h[s][0..31] as 16 f32x2
            ull hh[16];
            unsigned base = (unsigned)__cvta_generic_to_shared(hsrc + s*32);
            lds_v2b64(hh[0],  hh[1],  base +   0);
            lds_v2b64(hh[2],  hh[3],  base +  16);
            lds_v2b64(hh[4],  hh[5],  base +  32);
            lds_v2b64(hh[6],  hh[7],  base +  48);
            lds_v2b64(hh[8],  hh[9],  base +  64);
            lds_v2b64(hh[10], hh[11], base +  80);
            lds_v2b64(hh[12], hh[13], base +  96);
            lds_v2b64(hh[14], hh[15], base + 112);

            ull ar0 = packff(bR, 0.f),  ar1 = 0ull;
            ull az0 = packff(bZ, 0.f),  az1 = 0ull;
            ull an0 = packff(bhn, 0.f), an1 = 0ull;
#pragma unroll
            for (int k2 = 0; k2 < 16; k2 += 2){
                ar0 = ffma2(wr[k2],   hh[k2],   ar0);
                az0 = ffma2(wz[k2],   hh[k2],   az0);
                an0 = ffma2(wn[k2],   hh[k2],   an0);
                ar1 = ffma2(wr[k2+1], hh[k2+1], ar1);
                az1 = ffma2(wz[k2+1], hh[k2+1], az1);
                an1 = ffma2(wn[k2+1], hh[k2+1], an1);
            }
            float ar = hsum2(ar0, ar1);
            float az = hsum2(az0, az1);
            float an = hsum2(an0, an1);

            float xt   = xb[s*Tn + t];
            float hold = hsrc[s*32 + j];

            float r = fmaf(0.5f, tanhap(0.5f*fmaf(xt, wir, ar)), 0.5f);
            float z = fmaf(0.5f, tanhap(0.5f*fmaf(xt, wiz, az)), 0.5f);
            float xn = fmaf(xt, win, bxn);
            float nv = tanhap(fmaf(r, an, xn));
            float hnew = fmaf(z, hold - nv, nv);

            if (!last){
                hdst[s*32 + j] = hnew;
            } else {
                int m = m0 + s;
                int b = m / Nn, nn = m % Nn;
                g_h[((size_t)nn*Bn + b)*Hn + j] = hnew;   // coalesced across lanes
            }
        }
        __syncwarp();
        p ^= 1;
    }
}

// ---------------- dense matmul + self-loop init (+ optional bias+relu on input) ----------------
template<int CIN, int COUT, bool RELU>
__global__ void mm_init_kernel(const float* __restrict__ in,
                               const float* __restrict__ W,
                               const float* __restrict__ bin,
                               float* __restrict__ xw,
                               float* __restrict__ outbuf)
{
    __shared__ float sW[CIN*COUT];
    __shared__ float sb[CIN];
    int tid = threadIdx.x;
    for (int i = tid; i < CIN*COUT; i += blockDim.x) sW[i] = W[i];
    if (RELU && tid < CIN) sb[tid] = bin[tid];
    __syncthreads();

    int r = blockIdx.x*blockDim.x + tid;
    if (r >= Mn) return;
    int n = r / Bn;
    float di = g_dinv[n];
    float dd = di*di;                         // self-loop norm

    float v[CIN];
#pragma unroll
    for (int i = 0; i < CIN; i += 4){
        float4 t4 = *(const float4*)(in + (size_t)r*CIN + i);
        v[i]=t4.x; v[i+1]=t4.y; v[i+2]=t4.z; v[i+3]=t4.w;
    }
    if (RELU){
#pragma unroll
        for (int i = 0; i < CIN; i++) v[i] = fmaxf(v[i] + sb[i], 0.f);
    }
    float acc[COUT];
#pragma unroll
    for (int o = 0; o < COUT; o++) acc[o] = 0.f;
#pragma unroll
    for (int i = 0; i < CIN; i++){
        float vi = v[i];
#pragma unroll
        for (int o = 0; o < COUT; o++) acc[o] += vi * sW[i*COUT + o];
    }
    float* px = xw     + (size_t)r*COUT;
    float* po = outbuf + (size_t)r*COUT;
#pragma unroll
    for (int o = 0; o < COUT; o += 4){
        *(float4*)(px+o) = make_float4(acc[o],    acc[o+1],    acc[o+2],    acc[o+3]);
        *(float4*)(po+o) = make_float4(dd*acc[o], dd*acc[o+1], dd*acc[o+2], dd*acc[o+3]);
    }
}

// ---------------- edge scatter: one warp per edge, vectorized fp32 RED ----------------
__device__ __forceinline__ void red4(float* p, float4 v){
    asm volatile("red.global.add.v4.f32 [%0], {%1, %2, %3, %4};"
                 :: "l"(p), "f"(v.x), "f"(v.y), "f"(v.z), "f"(v.w) : "memory");
}

template<int C>
__global__ void scatter_kernel(const int* __restrict__ ei,
                               const float* __restrict__ ew,
                               const float* __restrict__ xw,
                               float* __restrict__ out, int E)
{
    int g    = blockIdx.x*blockDim.x + threadIdx.x;
    int warp = g >> 5;
    int lane = g & 31;
    if (warp >= E) return;

    int src = 0, tgt = 0; float nrm = 0.f;
    if (lane == 0){
        src = ei[warp];
        tgt = ei[E + warp];
        nrm = g_dinv[src] * ew[warp] * g_dinv[tgt];
    }
    src = __shfl_sync(0xffffffffu, src, 0);
    tgt = __shfl_sync(0xffffffffu, tgt, 0);
    nrm = __shfl_sync(0xffffffffu, nrm, 0);

    const float4* s = (const float4*)(xw + (size_t)src*(Bn*C));
    float*        d = out + (size_t)tgt*(Bn*C);
#pragma unroll
    for (int i = 0; i < (Bn*C)/128; i++){
        float4 v = s[lane + 32*i];
        v.x *= nrm; v.y *= nrm; v.z *= nrm; v.w *= nrm;
        red4(d + 4*(lane + 32*i), v);
    }
}

// ---------------- final linear head + [b][n] transpose ----------------
__global__ void final_kernel(const float* __restrict__ b2,
                             const float* __restrict__ Wfc,
                             const float* __restrict__ bfc,
                             float* __restrict__ y)
{
    int r = blockIdx.x*blockDim.x + threadIdx.x;
    if (r >= Mn) return;
    int n = r / Bn, b = r % Bn;
    const float* row = g_out2 + (size_t)r*On;
    float acc = bfc[0];
#pragma unroll
    for (int o = 0; o < On; o++) acc += (row[o] + b2[o]) * Wfc[o];
    y[(size_t)b*Nn + n] = acc;
}

// ---------------- launch ----------------
extern "C" void kernel_launch(void* const* d_in, const int* in_sizes, int n_in,
                              void* d_out, int out_size)
{
    const float* x    = (const float*)d_in[0];
    const int*   ei   = (const int*)  d_in[1];
    const float* ew   = (const float*)d_in[2];
    const float* w_ih = (const float*)d_in[3];
    const float* w_hh = (const float*)d_in[4];
    const float* b_ih = (const float*)d_in[5];
    const float* b_hh = (const float*)d_in[6];
    const float* W1   = (const float*)d_in[7];
    const float* b1   = (const float*)d_in[8];
    const float* W2   = (const float*)d_in[9];
    const float* b2   = (const float*)d_in[10];
    const float* Wfc  = (const float*)d_in[11];
    const float* bfc  = (const float*)d_in[12];
    float* y = (float*)d_out;
    int E = in_sizes[2];

    // resolve __device__ scratch addresses (not an allocation)
    float *p_h, *p_xw1, *p_out1, *p_xw2, *p_out2;
    cudaGetSymbolAddress((void**)&p_h,    g_h);
    cudaGetSymbolAddress((void**)&p_xw1,  g_xw1);
    cudaGetSymbolAddress((void**)&p_out1, g_out1);
    cudaGetSymbolAddress((void**)&p_xw2,  g_xw2);
    cudaGetSymbolAddress((void**)&p_out2, g_out2);

    // 1) gcn_norm
    deg_init_kernel<<<(Nn+255)/256, 256>>>();
    deg_acc_kernel <<<(E +255)/256, 256>>>(ei, ew, E);
    dinv_kernel    <<<(Nn+255)/256, 256>>>();

    // 2) GRU temporal encoder (warp-cooperative, register-resident weights)
    {
        const int smem = WPB * WSM * (int)sizeof(float);   // 45056 B
        cudaFuncSetAttribute(gru_kernel, cudaFuncAttributeMaxDynamicSharedMemorySize, smem);
        gru_kernel<<<GRU_GRID, GRU_TPB, smem>>>(x, w_ih, w_hh, b_ih, b_hh);  // 1250 blocks
    }

    // 3) conv1: xw1 = h@W1, out1 init = dinv^2*xw1 (self loop), then edge scatter
    mm_init_kernel<Hn, Hn, false><<<(Mn+127)/128, 128>>>(p_h, W1, nullptr, p_xw1, p_out1);
    scatter_kernel<Hn><<<((size_t)E*32 + 255)/256, 256>>>(ei, ew, p_xw1, p_out1, E);

    // 4) conv2: relu(out1+b1)@W2, self-loop init, edge scatter
    mm_init_kernel<Hn, On, true><<<(Mn+127)/128, 128>>>(p_out1, W2, b1, p_xw2, p_out2);
    scatter_kernel<On><<<((size_t)E*32 + 255)/256, 256>>>(ei, ew, p_xw2, p_out2, E);

    // 5) head: (out2+b2)@Wfc + bfc, transpose to [b][n]
    final_kernel<<<(Mn+255)/256, 256>>>(b2, Wfc, bfc, y);
}